// round 16
// baseline (speedup 1.0000x reference)
#include <cuda_runtime.h>

#define B_   32
#define N_   512
#define M_   512
#define D_   64
#define BIGF 1e10f
#define INV_LN2 1.4426950408889634f
#define LN2     0.6931471805599453f
#define BIGQ (BIGF * INV_LN2)

// Feed: g_F4[((b*4+w)*4+p)*FSTR4 + s*32 + l], row0 = 128w+4l+p (0-based),
// s = col + l (col = j-1). At DP step Tp all lanes read s = Tp-1: coalesced.
#define FSTR4 (544 * 32)
__device__ float g_F4[(size_t)B_ * 4 * 4 * FSTR4];

__device__ __forceinline__ float ex2f(float x) {
    float y; asm("ex2.approx.ftz.f32 %0, %1;" : "=f"(y) : "f"(x)); return y;
}
__device__ __forceinline__ float lg2f(float x) {
    float y; asm("lg2.approx.ftz.f32 %0, %1;" : "=f"(y) : "f"(x)); return y;
}

#define TS  64
#define SP  68
#define TSP 66

__global__ __launch_bounds__(256) void dist_kernel(const float* __restrict__ x,
                                                   const float* __restrict__ y) {
    __shared__ float Xs[D_ * SP];
    __shared__ float Ys[D_ * SP];
    __shared__ float xn[TS], yn[TS];

    const int b  = blockIdx.z;
    const int i0 = blockIdx.y * TS;
    const int j0 = blockIdx.x * TS;
    const float* xb = x + ((size_t)b * N_ + i0) * D_;
    const float* yb = y + ((size_t)b * M_ + j0) * D_;
    const int tid = threadIdx.x;

#pragma unroll
    for (int it = 0; it < 4; ++it) {
        int f = tid + it * 256, row = f & 63, c4 = f >> 6;
        float4 vx = *(const float4*)(xb + row * D_ + c4 * 4);
        float4 vy = *(const float4*)(yb + row * D_ + c4 * 4);
        Xs[(c4*4+0)*SP+row] = vx.x; Xs[(c4*4+1)*SP+row] = vx.y;
        Xs[(c4*4+2)*SP+row] = vx.z; Xs[(c4*4+3)*SP+row] = vx.w;
        Ys[(c4*4+0)*SP+row] = vy.x; Ys[(c4*4+1)*SP+row] = vy.y;
        Ys[(c4*4+2)*SP+row] = vy.z; Ys[(c4*4+3)*SP+row] = vy.w;
    }
    __syncthreads();

    if (tid < 64) {
        float s = 0.f;
#pragma unroll
        for (int k = 0; k < D_; ++k) { float v = Xs[k*SP+tid]; s = fmaf(v, v, s); }
        xn[tid] = s;
    } else if (tid < 128) {
        int r = tid - 64; float s = 0.f;
#pragma unroll
        for (int k = 0; k < D_; ++k) { float v = Ys[k*SP+r]; s = fmaf(v, v, s); }
        yn[r] = s;
    }
    __syncthreads();

    const int tx = tid & 15, ty = tid >> 4;
    const int ia = ty * 4, ja = tx * 4;
    float acc[4][4] = {};
#pragma unroll
    for (int k = 0; k < D_; ++k) {
        float4 a  = *(const float4*)&Xs[k*SP+ia];
        float4 bb = *(const float4*)&Ys[k*SP+ja];
        float av[4] = {a.x,a.y,a.z,a.w}, bv[4] = {bb.x,bb.y,bb.z,bb.w};
#pragma unroll
        for (int r = 0; r < 4; ++r)
#pragma unroll
            for (int c = 0; c < 4; ++c)
                acc[r][c] = fmaf(av[r], bv[c], acc[r][c]);
    }
    float x2v[4], y2v[4];
#pragma unroll
    for (int r = 0; r < 4; ++r) x2v[r] = xn[ia+r];
#pragma unroll
    for (int c = 0; c < 4; ++c) y2v[c] = yn[ja+c];

    __syncthreads();
    float* Ts = Xs;
#pragma unroll
    for (int r = 0; r < 4; ++r)
#pragma unroll
        for (int c = 0; c < 4; ++c)
            Ts[(ia+r)*TSP + ja+c] = fmaf(-2.f, acc[r][c], x2v[r]+y2v[c]) * INV_LN2;
    __syncthreads();

    // Drain into g_F4: local row lr = 4*ll + p (ll = l - l0), s = j0+l0+s_rel.
    const int Bq = blockIdx.y;
    const int w4 = Bq >> 1;
    const int l0 = (Bq & 1) * 16;
    const int g  = tid >> 4;           // 0..15
    const int ll = tid & 15;
    float* Fb = g_F4 + ((size_t)(b * 4 + w4) * 4) * FSTR4;
#pragma unroll
    for (int it = 0; it < 20; ++it) {
        int item = it * 16 + g;        // 0..319
        int p = item & 3, s_rel = item >> 2;
        int lv = s_rel - ll;
        if (lv >= 0 && lv < 64)
            Fb[(size_t)p * FSTR4 + (j0 + l0 + s_rel) * 32 + (l0 + ll)]
                = Ts[(4*ll + p) * TSP + lv];
    }
}

// ---------------------------------------------------------------------------
// soft-DTW: 4 warps/batch; lane l of warp w owns rows 128w+4l+{1..4}.
// Deferred-log (q,s), 3-exp softmin, 23 rounds x 32 steps, warp lag 2 rounds.
// ---------------------------------------------------------------------------
#define NR4 23

template <int MODE, int COFF>   // MODE: 0 head, 1 clean, 2 tail
__device__ __forceinline__ void half16(
    int rbase, int l, bool pR, bool pW, bool w0l0,
    const float2* __restrict__ ringrd, float2* __restrict__ ringwr,
    const float* __restrict__ d0, const float* __restrict__ d1,
    const float* __restrict__ d2, const float* __restrict__ d3,
    float& q0, float& s0, float& q1, float& s1,
    float& q2, float& s2, float& q3, float& s3,
    float& hq, float& hs)
{
#pragma unroll
    for (int cc = 0; cc < 16; ++cc) {
        const int c  = COFF + cc;
        const int Tp = rbase + cc;

        float sq = __shfl_up_sync(0xffffffffu, q3, 1);
        float ss = __shfl_up_sync(0xffffffffu, s3, 1);
        if (pR) { float2 rv = ringrd[Tp & 127]; sq = rv.x; ss = rv.y; }

        float h0 = hq, g0 = hs;
        if (MODE == 0 && COFF == 0 && cc == 0 && w0l0) { h0 = 0.f; g0 = 1.f; }

        float m0 = fminf(fminf(h0, q0), sq);
        float n0 = fmaf(g0, ex2f(m0 - h0), fmaf(ss, ex2f(m0 - sq), s0 * ex2f(m0 - q0)));
        float p0 = d0[cc] + m0;

        float m1 = fminf(fminf(q0, q1), p0);
        float n1 = fmaf(s0, ex2f(m1 - q0), fmaf(n0, ex2f(m1 - p0), s1 * ex2f(m1 - q1)));
        float p1 = d1[cc] + m1;

        float m2 = fminf(fminf(q1, q2), p1);
        float n2 = fmaf(s1, ex2f(m2 - q1), fmaf(n1, ex2f(m2 - p1), s2 * ex2f(m2 - q2)));
        float p2 = d2[cc] + m2;

        float m3 = fminf(fminf(q2, q3), p2);
        float n3 = fmaf(s2, ex2f(m3 - q2), fmaf(n2, ex2f(m3 - p2), s3 * ex2f(m3 - q3)));
        float p3 = d3[cc] + m3;

        hq = sq; hs = ss;

        bool actc = true;
        if (MODE == 0) actc = (c >= l);
        if (MODE == 2) actc = (c < l);
        if (actc) {
            q0 = p0; s0 = n0; q1 = p1; s1 = n1;
            q2 = p2; s2 = n2; q3 = p3; s3 = n3;
        }
        bool wr = pW && (MODE == 1 || actc);
        if (wr) ringwr[(Tp - 31) & 127] = make_float2(q3, s3);
    }
}

__global__ void __launch_bounds__(128, 1) dtw_kernel(float* __restrict__ out) {
    __shared__ float2 ring[5][128];          // row 4 = constant BIGQ row

    const int b   = blockIdx.x;
    const int tid = threadIdx.x;
    const int w   = tid >> 5;
    const int l   = tid & 31;

    if (tid < 128) ring[4][tid] = make_float2(BIGQ, 1.f);

    const bool pR   = (l == 0);
    const bool pW   = (l == 31);
    const bool w0l0 = (w == 0) && (l == 0);
    const float2* ringrd = (w == 0) ? ring[4] : ring[w - 1];
    float2*       ringwr = ring[w];

    const float* F0 = g_F4 + ((size_t)(b * 4 + w) * 4 + 0) * FSTR4 + l;
    const float* F1 = F0 + FSTR4;
    const float* F2 = F1 + FSTR4;
    const float* F3 = F2 + FSTR4;

    float q0 = BIGQ, s0 = 1.f, q1 = BIGQ, s1 = 1.f;
    float q2 = BIGQ, s2 = 1.f, q3 = BIGQ, s3 = 1.f;
    float hq = BIGQ, hs = 1.f;
    float a0[64], a1[64];                    // [p][16] flat, two half-buffers

    if (w == 0) {
#pragma unroll
        for (int c = 0; c < 16; ++c) {
            a0[c]    = __ldg(F0 + c*32); a0[16+c] = __ldg(F1 + c*32);
            a0[32+c] = __ldg(F2 + c*32); a0[48+c] = __ldg(F3 + c*32);
        }
    }
    __syncthreads();

    for (int r = 0; r < NR4; ++r) {
        const int rho = r - 2 * w;
        if (rho >= 0 && rho <= 16) {
            const int sb = rho * 32;
            // prefetch this round's half1 (consumed after half0: 16-step slack)
#pragma unroll
            for (int c = 0; c < 16; ++c) {
                a1[c]    = __ldg(F0 + (sb+16+c)*32); a1[16+c] = __ldg(F1 + (sb+16+c)*32);
                a1[32+c] = __ldg(F2 + (sb+16+c)*32); a1[48+c] = __ldg(F3 + (sb+16+c)*32);
            }
            const int rbase = sb + 1;
            if (rho == 0)
                half16<0,0>(rbase, l, pR, pW, w0l0, ringrd, ringwr,
                            a0, a0+16, a0+32, a0+48, q0,s0,q1,s1,q2,s2,q3,s3, hq,hs);
            else if (rho < 16)
                half16<1,0>(rbase, l, pR, pW, w0l0, ringrd, ringwr,
                            a0, a0+16, a0+32, a0+48, q0,s0,q1,s1,q2,s2,q3,s3, hq,hs);
            else
                half16<2,0>(rbase, l, pR, pW, w0l0, ringrd, ringwr,
                            a0, a0+16, a0+32, a0+48, q0,s0,q1,s1,q2,s2,q3,s3, hq,hs);

            if (rho < 16) {                  // prefetch next round's half0
#pragma unroll
                for (int c = 0; c < 16; ++c) {
                    a0[c]    = __ldg(F0 + (sb+32+c)*32); a0[16+c] = __ldg(F1 + (sb+32+c)*32);
                    a0[32+c] = __ldg(F2 + (sb+32+c)*32); a0[48+c] = __ldg(F3 + (sb+32+c)*32);
                }
            }
            if (rho == 0)
                half16<0,16>(rbase+16, l, pR, pW, w0l0, ringrd, ringwr,
                             a1, a1+16, a1+32, a1+48, q0,s0,q1,s1,q2,s2,q3,s3, hq,hs);
            else if (rho < 16)
                half16<1,16>(rbase+16, l, pR, pW, w0l0, ringrd, ringwr,
                             a1, a1+16, a1+32, a1+48, q0,s0,q1,s1,q2,s2,q3,s3, hq,hs);
            else
                half16<2,16>(rbase+16, l, pR, pW, w0l0, ringrd, ringwr,
                             a1, a1+16, a1+32, a1+48, q0,s0,q1,s1,q2,s2,q3,s3, hq,hs);

            q0 -= lg2f(s0); s0 = 1.f;        // value-preserving renorms
            q1 -= lg2f(s1); s1 = 1.f;
            q2 -= lg2f(s2); s2 = 1.f;
            q3 -= lg2f(s3); s3 = 1.f;
        } else if (rho == -1) {              // prime my first half0
#pragma unroll
            for (int c = 0; c < 16; ++c) {
                a0[c]    = __ldg(F0 + c*32); a0[16+c] = __ldg(F1 + c*32);
                a0[32+c] = __ldg(F2 + c*32); a0[48+c] = __ldg(F3 + c*32);
            }
        }
        __syncthreads();
    }

    if (w == 3 && l == 31)
        out[b] = (q3 - lg2f(s3)) * LN2;      // R[512][512]
}

extern "C" void kernel_launch(void* const* d_in, const int* in_sizes, int n_in,
                              void* d_out, int out_size) {
    const float* x = (const float*)d_in[0];
    const float* y = (const float*)d_in[1];
    float* out = (float*)d_out;

    dim3 dgrid(M_ / TS, N_ / TS, B_);
    dist_kernel<<<dgrid, 256>>>(x, y);
    dtw_kernel<<<B_, 128>>>(out);
}

// round 17
// speedup vs baseline: 1.0346x; 1.0346x over previous
#include <cuda_runtime.h>

#define B_   32
#define N_   512
#define M_   512
#define D_   64
#define BIGF 1e10f
#define INV_LN2 1.4426950408889634f
#define LN2     0.6931471805599453f
#define BIGQ (BIGF * INV_LN2)

// Feed: g_F[((b*8+w)*2+p)*FSTRIDE + s*32 + l], row = 64w+2l+p, s = col + l.
#define FSTRIDE (544 * 32)
__device__ float g_F[(size_t)B_ * 8 * 2 * FSTRIDE];

__device__ __forceinline__ float ex2f(float x) {
    float y; asm("ex2.approx.ftz.f32 %0, %1;" : "=f"(y) : "f"(x)); return y;
}
__device__ __forceinline__ float lg2f(float x) {
    float y; asm("lg2.approx.ftz.f32 %0, %1;" : "=f"(y) : "f"(x)); return y;
}

#define TS  64
#define SP  68
#define TSP 66

__global__ __launch_bounds__(256) void dist_kernel(const float* __restrict__ x,
                                                   const float* __restrict__ y) {
    __shared__ float Xs[D_ * SP];
    __shared__ float Ys[D_ * SP];
    __shared__ float xn[TS], yn[TS];

    const int b  = blockIdx.z;
    const int i0 = blockIdx.y * TS;
    const int j0 = blockIdx.x * TS;
    const float* xb = x + ((size_t)b * N_ + i0) * D_;
    const float* yb = y + ((size_t)b * M_ + j0) * D_;
    const int tid = threadIdx.x;

#pragma unroll
    for (int it = 0; it < 4; ++it) {
        int f = tid + it * 256, row = f & 63, c4 = f >> 6;
        float4 vx = *(const float4*)(xb + row * D_ + c4 * 4);
        float4 vy = *(const float4*)(yb + row * D_ + c4 * 4);
        Xs[(c4*4+0)*SP+row] = vx.x; Xs[(c4*4+1)*SP+row] = vx.y;
        Xs[(c4*4+2)*SP+row] = vx.z; Xs[(c4*4+3)*SP+row] = vx.w;
        Ys[(c4*4+0)*SP+row] = vy.x; Ys[(c4*4+1)*SP+row] = vy.y;
        Ys[(c4*4+2)*SP+row] = vy.z; Ys[(c4*4+3)*SP+row] = vy.w;
    }
    __syncthreads();

    if (tid < 64) {
        float s = 0.f;
#pragma unroll
        for (int k = 0; k < D_; ++k) { float v = Xs[k*SP+tid]; s = fmaf(v, v, s); }
        xn[tid] = s;
    } else if (tid < 128) {
        int r = tid - 64; float s = 0.f;
#pragma unroll
        for (int k = 0; k < D_; ++k) { float v = Ys[k*SP+r]; s = fmaf(v, v, s); }
        yn[r] = s;
    }
    __syncthreads();

    const int tx = tid & 15, ty = tid >> 4;
    const int ia = ty * 4, ja = tx * 4;
    float acc[4][4] = {};
#pragma unroll
    for (int k = 0; k < D_; ++k) {
        float4 a  = *(const float4*)&Xs[k*SP+ia];
        float4 bb = *(const float4*)&Ys[k*SP+ja];
        float av[4] = {a.x,a.y,a.z,a.w}, bv[4] = {bb.x,bb.y,bb.z,bb.w};
#pragma unroll
        for (int r = 0; r < 4; ++r)
#pragma unroll
            for (int c = 0; c < 4; ++c)
                acc[r][c] = fmaf(av[r], bv[c], acc[r][c]);
    }
    float x2v[4], y2v[4];
#pragma unroll
    for (int r = 0; r < 4; ++r) x2v[r] = xn[ia+r];
#pragma unroll
    for (int c = 0; c < 4; ++c) y2v[c] = yn[ja+c];

    __syncthreads();
    float* Ts = Xs;
#pragma unroll
    for (int r = 0; r < 4; ++r)
#pragma unroll
        for (int c = 0; c < 4; ++c)
            Ts[(ia+r)*TSP + ja+c] = fmaf(-2.f, acc[r][c], x2v[r]+y2v[c]) * INV_LN2;
    __syncthreads();

    // Drain: (row=2l+p, col=lv) -> g_F[(b*8+wD)*2+p][(j0+s_rel)*32+l], s_rel = lv+l.
    const int wD = blockIdx.y, wd = tid >> 5, l = tid & 31;
    float* F0 = g_F + ((size_t)(b * 8 + wD) * 2) * FSTRIDE;
#pragma unroll
    for (int p = 0; p < 2; ++p) {
        float* Fp = F0 + p * FSTRIDE;
#pragma unroll
        for (int it = 0; it < 16; ++it) {
            int s_rel = it * 8 + wd;
            int lv = s_rel - l;
            if (lv >= 0 && lv < 64)
                Fp[(j0 + s_rel) * 32 + l] = Ts[(2*l+p)*TSP + lv];
        }
    }
}

// ---------------------------------------------------------------------------
// soft-DTW: 8 warps/batch; lane l of warp w owns rows 64w+2l+1, 64w+2l+2.
// Deferred-log (q,s); 2-exp SELECT softmin with the local pair reduced BEFORE
// the shfl value is consumed (short post-shfl chain, 4 ex2/step).
// 31 rounds x 32 steps, warp lag 2 rounds, smem boundary ring.
// ---------------------------------------------------------------------------
#define NR2 31

// exact softmin combine: result (qr,sr) for terms (qa,sa),(qb,sb),(qx,sx)
// where (qa,sa),(qb,sb) are LOCAL (reduced first) and (qx,sx) arrives late.
__device__ __forceinline__ void soft3(
    float qa, float sa, float qb, float sb,   // local pair
    float qx, float sx,                       // late cross term
    float d, float& qr, float& sr)
{
    // local pair reduce (no dependence on qx)
    float lo = fminf(qa, qb);
    float hi = fmaxf(qa, qb);
    float sl = (qa <= qb) ? sa : sb;
    float sh = (qa <= qb) ? sb : sa;
    float pp = fmaf(sh, ex2f(lo - hi), sl);   // pair sum at scale lo
    // cross combine (post-late-value chain: fmin, ex2, fmaf)
    float m  = fminf(lo, qx);
    float e  = ex2f(m - fmaxf(lo, qx));
    float t1 = (qx < lo) ? pp : sx;
    float t2 = (qx < lo) ? sx : pp;
    sr = fmaf(t1, e, t2);
    qr = d + m;
}

template <int MODE, int COFF>   // MODE: 0 head, 1 clean, 2 tail
__device__ __forceinline__ void half16(
    int rbase, int l, bool pR, bool pW, bool w0l0,
    const float2* __restrict__ ringrd, float2* __restrict__ ringwr,
    const float* __restrict__ dA, const float* __restrict__ dB,
    float& qT, float& sT, float& qB, float& sB, float& hq, float& hs)
{
#pragma unroll
    for (int cc = 0; cc < 16; ++cc) {
        const int c = COFF + cc;

        float sq = __shfl_up_sync(0xffffffffu, qB, 1);
        float ss = __shfl_up_sync(0xffffffffu, sB, 1);
        if (pR) { float2 rv = ringrd[(rbase + cc) & 127]; sq = rv.x; ss = rv.y; }

        float q0 = hq, s0 = hs;
        if (MODE == 0 && COFF == 0 && cc == 0 && w0l0) { q0 = 0.f; s0 = 1.f; }  // R[0][0]

        // top cell: local pair (q0,s0)=(R[i-1][j-1]), (qT,sT)=(R[i][j-1]);
        // late term = (sq,ss)=(R[i-1][j]) from shfl/ring.
        float qnT, snT;
        soft3(q0, s0, qT, sT, sq, ss, dA[cc], qnT, snT);

        // bottom cell: local pair (qT,sT)=old top=(R[i-1][j-1]), (qB,sB);
        // late term = (qnT,snT)=(R[i-1][j]).
        float qnB, snB;
        soft3(qT, sT, qB, sB, qnT, snT, dB[cc], qnB, snB);

        bool actc = true;
        if (MODE == 0) actc = (c >= l);
        if (MODE == 2) actc = (c < l);
        if (actc) { qT = qnT; sT = snT; qB = qnB; sB = snB; }
        hq = sq; hs = ss;

        bool wr = pW && (MODE == 1 || actc);
        if (wr) ringwr[(rbase + cc - 31) & 127] = make_float2(qB, sB);
    }
}

__global__ void __launch_bounds__(256, 1) dtw_kernel(float* __restrict__ out) {
    __shared__ float2 ring[9][128];          // row 8 = constant BIGQ row

    const int b   = blockIdx.x;
    const int tid = threadIdx.x;
    const int w   = tid >> 5;
    const int l   = tid & 31;

    if (tid < 128) ring[8][tid] = make_float2(BIGQ, 1.f);

    const bool pR   = (l == 0);
    const bool pW   = (l == 31);
    const bool w0l0 = (w == 0) && (l == 0);
    const float2* ringrd = (w == 0) ? ring[8] : ring[w - 1];
    float2*       ringwr = ring[w];

    const float* FT = g_F + ((size_t)(b * 8 + w) * 2) * FSTRIDE + l;
    const float* FB = FT + FSTRIDE;

    float qT = BIGQ, sT = 1.f, qB = BIGQ, sB = 1.f;
    float hq = BIGQ, hs = 1.f;
    float a0[16], b0[16], a1[16], b1[16];

    if (w == 0) {
#pragma unroll
        for (int c = 0; c < 16; ++c) { a0[c] = __ldg(FT + c*32); b0[c] = __ldg(FB + c*32); }
    }
    __syncthreads();

    for (int r = 0; r < NR2; ++r) {
        const int rho = r - 2 * w;
        if (rho >= 0 && rho <= 16) {
            const int sb = rho * 32;
#pragma unroll
            for (int c = 0; c < 16; ++c) {       // prefetch this round's half1
                a1[c] = __ldg(FT + (sb + 16 + c)*32);
                b1[c] = __ldg(FB + (sb + 16 + c)*32);
            }
            const int rbase = sb + 1;
            if (rho == 0)
                half16<0, 0>(rbase, l, pR, pW, w0l0, ringrd, ringwr, a0, b0, qT, sT, qB, sB, hq, hs);
            else if (rho < 16)
                half16<1, 0>(rbase, l, pR, pW, w0l0, ringrd, ringwr, a0, b0, qT, sT, qB, sB, hq, hs);
            else
                half16<2, 0>(rbase, l, pR, pW, w0l0, ringrd, ringwr, a0, b0, qT, sT, qB, sB, hq, hs);

            if (rho < 16) {                      // prefetch next round's half0
#pragma unroll
                for (int c = 0; c < 16; ++c) {
                    a0[c] = __ldg(FT + (sb + 32 + c)*32);
                    b0[c] = __ldg(FB + (sb + 32 + c)*32);
                }
            }
            if (rho == 0)
                half16<0, 16>(rbase + 16, l, pR, pW, w0l0, ringrd, ringwr, a1, b1, qT, sT, qB, sB, hq, hs);
            else if (rho < 16)
                half16<1, 16>(rbase + 16, l, pR, pW, w0l0, ringrd, ringwr, a1, b1, qT, sT, qB, sB, hq, hs);
            else
                half16<2, 16>(rbase + 16, l, pR, pW, w0l0, ringrd, ringwr, a1, b1, qT, sT, qB, sB, hq, hs);

            qT -= lg2f(sT); sT = 1.f;            // value-preserving renorm
            qB -= lg2f(sB); sB = 1.f;
        } else if (rho == -1) {                  // prime my first half0
#pragma unroll
            for (int c = 0; c < 16; ++c) { a0[c] = __ldg(FT + c*32); b0[c] = __ldg(FB + c*32); }
        }
        __syncthreads();
    }

    if (w == 7 && l == 31)
        out[b] = (qB - lg2f(sB)) * LN2;          // R[512][512]
}

extern "C" void kernel_launch(void* const* d_in, const int* in_sizes, int n_in,
                              void* d_out, int out_size) {
    const float* x = (const float*)d_in[0];
    const float* y = (const float*)d_in[1];
    float* out = (float*)d_out;

    dim3 dgrid(M_ / TS, N_ / TS, B_);
    dist_kernel<<<dgrid, 256>>>(x, y);
    dtw_kernel<<<B_, 256>>>(out);
}